// round 7
// baseline (speedup 1.0000x reference)
#include <cuda_runtime.h>
#include <stdint.h>

// Problem constants
#define NUM_STEPS 25
#define BATCH     4096
#define NIN       784
#define NHID      1000
#define NOUT      10
#define MTOT      (NUM_STEPS * BATCH)   // 102400
#define BETA      0.95f
#define THRESH    1.0f

typedef unsigned long long ull;

// Scratch (device globals; no runtime allocation allowed)
__device__ float    g_cur1[(size_t)MTOT * NHID];     // [t*B+b][h]
__device__ uint32_t g_maskT[(size_t)32 * MTOT];      // spk1 bits, [word][row]
__device__ float    g_cur2[(size_t)MTOT * NOUT];     // [t*B+b][o]

// Opaque constants: volatile loads make these unknown to ptxas, so the
// FFMA2-based unfused MAC below can never be strength-reduced or re-fused.
__device__ volatile ull g_zero2 = 0ull;                     // {+0.f, +0.f}
__device__ volatile ull g_one2  = 0x3F8000003F800000ULL;    // {1.f, 1.f}

// ---------------------------------------------------------------------------
// Packed unfused MAC, fusion-proof:
//   p   = fma.rn.f32x2(a, b, Z)    == rn(a*b)   per lane   (Z = {0,0})
//   acc = fma.rn.f32x2(p, ONE, acc)== rn(p+acc) per lane   (ONE = {1,1})
// Exactly the reference's two-rounding sequence; nothing for ptxas to contract.
// ---------------------------------------------------------------------------
static __device__ __forceinline__ ull splat2(float v) {
    ull r;
    asm("mov.b64 %0, {%1, %1};" : "=l"(r) : "r"(__float_as_uint(v)));
    return r;
}
static __device__ __forceinline__ void mac2(ull& acc, ull a, ull b,
                                            ull z2, ull o2) {
    ull p;
    asm("fma.rn.f32x2 %0, %1, %2, %3;" : "=l"(p) : "l"(a), "l"(b), "l"(z2));
    asm("fma.rn.f32x2 %0, %1, %2, %0;" : "+l"(acc) : "l"(p), "l"(o2));
}

// ---------------------------------------------------------------------------
// Kernel 1: cur1 = X[102400,784] @ W1[1000,784]^T + b1
// Reference numerics (FROZEN): per output, single fp32 accumulator,
//   acc = rn(acc + rn(a_k*b_k)), k ascending 0..783, one rn bias add.
// Tile 128x128x16, 256 threads, 8x8 outputs/thread (4 packed pairs wide).
// ---------------------------------------------------------------------------
#define BM 128
#define BN 128
#define BK 16
#define LDA2 130          // ull stride for splatted A tile (even -> 16B align)
#define LDB  132          // float stride for B tile

__global__ void __launch_bounds__(256, 2)
gemm1_kernel(const float* __restrict__ X, const float* __restrict__ W1,
             const float* __restrict__ b1)
{
    __shared__ ull   As2[BK * LDA2];   // [k][row] = {x, x} splatted pairs
    __shared__ float Bs[BK * LDB];     // [k][col]

    const ull z2 = g_zero2;            // opaque {0,0}
    const ull o2 = g_one2;             // opaque {1,1}

    const int tid = threadIdx.x;
    const int bm  = blockIdx.y * BM;
    const int bn  = blockIdx.x * BN;

    // loader mapping: 256 threads load 128 rows x 16 cols as float4
    const int lr  = tid >> 2;          // 0..63
    const int lc4 = (tid & 3) * 4;     // 0,4,8,12

    // compute mapping
    const int tx   = tid & 15;
    const int ty   = tid >> 4;
    const int row0 = ty * 8;
    const int col0 = tx * 8;

    ull acc2[8][4];                    // [i][jp] = packed {acc_j, acc_j+1}
#pragma unroll
    for (int i = 0; i < 8; i++)
#pragma unroll
        for (int jp = 0; jp < 4; jp++) acc2[i][jp] = 0ull;

    for (int k0 = 0; k0 < NIN; k0 += BK) {
#pragma unroll
        for (int r = 0; r < 2; r++) {
            const int arow = lr + r * 64;
            // A tile (X): in-bounds (M % 128 == 0, K % 16 == 0); store splatted
            float4 va = *(const float4*)(X + (size_t)(bm + arow) * NIN + k0 + lc4);
            As2[(lc4 + 0) * LDA2 + arow] = splat2(va.x);
            As2[(lc4 + 1) * LDA2 + arow] = splat2(va.y);
            As2[(lc4 + 2) * LDA2 + arow] = splat2(va.z);
            As2[(lc4 + 3) * LDA2 + arow] = splat2(va.w);
            // B tile (W1): guard n < 1000
            const int n = bn + arow;
            float4 vb = make_float4(0.f, 0.f, 0.f, 0.f);
            if (n < NHID)
                vb = *(const float4*)(W1 + (size_t)n * NIN + k0 + lc4);
            Bs[(lc4 + 0) * LDB + arow] = vb.x;
            Bs[(lc4 + 1) * LDB + arow] = vb.y;
            Bs[(lc4 + 2) * LDB + arow] = vb.z;
            Bs[(lc4 + 3) * LDB + arow] = vb.w;
        }
        __syncthreads();

#pragma unroll
        for (int k = 0; k < BK; k++) {   // ascending k; packed unfused mul+add
            // B pairs: 8 floats = 4 packed pairs, via 2x LDS.128
            const ulonglong2 bq0 = *(const ulonglong2*)&Bs[k * LDB + col0];
            const ulonglong2 bq1 = *(const ulonglong2*)&Bs[k * LDB + col0 + 4];
            // A splats: 8 ull, via 4x LDS.128 (broadcast within warp)
            const ulonglong2 aq0 = *(const ulonglong2*)&As2[k * LDA2 + row0];
            const ulonglong2 aq1 = *(const ulonglong2*)&As2[k * LDA2 + row0 + 2];
            const ulonglong2 aq2 = *(const ulonglong2*)&As2[k * LDA2 + row0 + 4];
            const ulonglong2 aq3 = *(const ulonglong2*)&As2[k * LDA2 + row0 + 6];
            const ull aa[8] = {aq0.x, aq0.y, aq1.x, aq1.y,
                               aq2.x, aq2.y, aq3.x, aq3.y};
#pragma unroll
            for (int i = 0; i < 8; i++) {
                mac2(acc2[i][0], aa[i], bq0.x, z2, o2);
                mac2(acc2[i][1], aa[i], bq0.y, z2, o2);
                mac2(acc2[i][2], aa[i], bq1.x, z2, o2);
                mac2(acc2[i][3], aa[i], bq1.y, z2, o2);
            }
        }
        __syncthreads();
    }

    // epilogue: unpack, single rn bias add, store cur1
#pragma unroll
    for (int i = 0; i < 8; i++) {
        const int m = bm + row0 + i;
#pragma unroll
        for (int jp = 0; jp < 4; jp++) {
            uint32_t lo, hi;
            asm("mov.b64 {%0, %1}, %2;" : "=r"(lo), "=r"(hi) : "l"(acc2[i][jp]));
            const int n0 = bn + col0 + jp * 2;
            if (n0 < NHID)
                g_cur1[(size_t)m * NHID + n0] =
                    __fadd_rn(__uint_as_float(lo), __ldg(&b1[n0]));
            if (n0 + 1 < NHID)
                g_cur1[(size_t)m * NHID + n0 + 1] =
                    __fadd_rn(__uint_as_float(hi), __ldg(&b1[n0 + 1]));
        }
    }
}

// ---------------------------------------------------------------------------
// Kernel 2: layer-1 leaky-integrate recurrence; spk1 -> transposed bitmask.
// Strict rn ops, unfused, exact reference op order: ((B*mem)+cur)-reset.
// ---------------------------------------------------------------------------
__global__ void __launch_bounds__(256)
rec1_kernel()
{
    const int warp  = (blockIdx.x * blockDim.x + threadIdx.x) >> 5;
    const int lane  = threadIdx.x & 31;
    const int chunk = warp & 31;
    const int b     = warp >> 5;
    if (b >= BATCH) return;

    const int h = chunk * 32 + lane;
    const bool valid = (h < NHID);

    float mem = 0.f;
#pragma unroll
    for (int t = 0; t < NUM_STEPS; t++) {
        const float c = valid ? g_cur1[((size_t)t * BATCH + b) * NHID + h] : -1.f;
        const float rst = (mem > THRESH) ? THRESH : 0.f;
        mem = __fsub_rn(__fadd_rn(__fmul_rn(BETA, mem), c), rst);
        const uint32_t w = __ballot_sync(0xffffffffu, mem > THRESH);
        if (lane == 0)
            g_maskT[(size_t)chunk * MTOT + (size_t)t * BATCH + b] = w;
    }
}

// ---------------------------------------------------------------------------
// Kernel 3: cur2 = spk1 @ W2^T + b2.  One thread per row, ascending-h chain.
// With spk in {0,1}, rn(spk*w) is exact, so the FMA chain is bit-identical
// to an unfused ascending chain.
// ---------------------------------------------------------------------------
#define W2LD 12

__global__ void __launch_bounds__(256)
gemm2_kernel(const float* __restrict__ W2, const float* __restrict__ b2)
{
    __shared__ float W2t[1000 * W2LD];   // [h][o], padded
    for (int i = threadIdx.x; i < NOUT * NHID; i += 256) {
        const int o = i / NHID, h = i - o * NHID;
        W2t[h * W2LD + o] = W2[i];
    }
    __syncthreads();

    const int row = blockIdx.x * 256 + threadIdx.x;   // 0..102399

    float acc[NOUT];
#pragma unroll
    for (int o = 0; o < NOUT; o++) acc[o] = 0.f;

#pragma unroll 1
    for (int wd = 0; wd < 32; wd++) {
        const uint32_t w = g_maskT[(size_t)wd * MTOT + row];
        const int nb = (wd < 31) ? 32 : (NHID - 31 * 32);   // 32 or 8
#pragma unroll 8
        for (int bit = 0; bit < nb; bit++) {
            const float f = (float)((w >> bit) & 1u);
            const int h = wd * 32 + bit;
            const float* wrow = &W2t[h * W2LD];
            float4 w0 = *(const float4*)(wrow);
            float4 w1 = *(const float4*)(wrow + 4);
            float2 w2v = *(const float2*)(wrow + 8);
            acc[0] = __fmaf_rn(f, w0.x, acc[0]);
            acc[1] = __fmaf_rn(f, w0.y, acc[1]);
            acc[2] = __fmaf_rn(f, w0.z, acc[2]);
            acc[3] = __fmaf_rn(f, w0.w, acc[3]);
            acc[4] = __fmaf_rn(f, w1.x, acc[4]);
            acc[5] = __fmaf_rn(f, w1.y, acc[5]);
            acc[6] = __fmaf_rn(f, w1.z, acc[6]);
            acc[7] = __fmaf_rn(f, w1.w, acc[7]);
            acc[8] = __fmaf_rn(f, w2v.x, acc[8]);
            acc[9] = __fmaf_rn(f, w2v.y, acc[9]);
        }
    }

    float* out = g_cur2 + (size_t)row * NOUT;
#pragma unroll
    for (int o = 0; o < NOUT; o++)
        out[o] = __fadd_rn(acc[o], __ldg(&b2[o]));
}

// ---------------------------------------------------------------------------
// Kernel 4: layer-2 recurrence + write spk_rec / mem_rec outputs.
// Output layout: [spk_rec (25,4096,10) | mem_rec (25,4096,10)]
// ---------------------------------------------------------------------------
__global__ void __launch_bounds__(256)
rec2_kernel(float* __restrict__ out)
{
    const int idx = blockIdx.x * blockDim.x + threadIdx.x;   // b*10 + o
    if (idx >= BATCH * NOUT) return;

    float mem = 0.f;
#pragma unroll
    for (int t = 0; t < NUM_STEPS; t++) {
        const float c   = g_cur2[(size_t)t * (BATCH * NOUT) + idx];
        const float rst = (mem > THRESH) ? THRESH : 0.f;
        mem = __fsub_rn(__fadd_rn(__fmul_rn(BETA, mem), c), rst);
        const float spk = (mem > THRESH) ? 1.f : 0.f;
        out[(size_t)t * (BATCH * NOUT) + idx] = spk;
        out[(size_t)NUM_STEPS * BATCH * NOUT + (size_t)t * (BATCH * NOUT) + idx] = mem;
    }
}

// ---------------------------------------------------------------------------
extern "C" void kernel_launch(void* const* d_in, const int* in_sizes, int n_in,
                              void* d_out, int out_size)
{
    const float* x  = (const float*)d_in[0];   // [25,4096,784]
    const float* W1 = (const float*)d_in[1];   // [1000,784]
    const float* b1 = (const float*)d_in[2];   // [1000]
    const float* W2 = (const float*)d_in[3];   // [10,1000]
    const float* b2 = (const float*)d_in[4];   // [10]
    float* out = (float*)d_out;

    dim3 g1((NHID + BN - 1) / BN, MTOT / BM);  // (8, 800)
    gemm1_kernel<<<g1, 256>>>(x, W1, b1);

    rec1_kernel<<<(BATCH * 32) / 8, 256>>>();

    gemm2_kernel<<<MTOT / 256, 256>>>(W2, b2);

    rec2_kernel<<<(BATCH * NOUT + 255) / 256, 256>>>(out);
}

// round 8
// speedup vs baseline: 1.2040x; 1.2040x over previous
#include <cuda_runtime.h>
#include <stdint.h>

// Problem constants
#define NUM_STEPS 25
#define BATCH     4096
#define NIN       784
#define NHID      1000
#define NOUT      10
#define MTOT      (NUM_STEPS * BATCH)   // 102400
#define BETA      0.95f
#define THRESH    1.0f

// Scratch (device globals; no runtime allocation allowed)
__device__ float    g_cur1[(size_t)MTOT * NHID];     // [t*B+b][h]
__device__ uint32_t g_maskT[(size_t)32 * MTOT];      // spk1 bits, [word][row]
__device__ float    g_cur2[(size_t)MTOT * NOUT];     // [t*B+b][o]

// ---------------------------------------------------------------------------
// Kernel 1: cur1 = X[102400,784] @ W1[1000,784]^T + b1
// Reference numerics (FROZEN): per output, single fp32 accumulator,
//   acc = rn(acc + rn(a_k*b_k)), k ascending 0..783, then one rn bias add.
// Scalar __fmul_rn/__fadd_rn (contraction-proof). Double-buffered smem with
// register prefetch: LDG(next tile) issued before compute(current tile),
// STS after compute, one __syncthreads per tile -> fp pipe never drains.
// Tile 128x128x16, 256 threads, 8x8 register tile.
// ---------------------------------------------------------------------------
#define BM 128
#define BN 128
#define BK 16
#define NT (NIN / BK)     // 49 k-tiles
#define LDA (BM + 4)
#define LDB (BN + 4)

__global__ void __launch_bounds__(256, 2)
gemm1_kernel(const float* __restrict__ X, const float* __restrict__ W1,
             const float* __restrict__ b1)
{
    __shared__ float As[2][BK * LDA];
    __shared__ float Bs[2][BK * LDB];

    const int tid = threadIdx.x;
    const int bm  = blockIdx.y * BM;
    const int bn  = blockIdx.x * BN;

    // loader mapping: 256 threads load 128 rows x 16 cols as float4 (x2 rows)
    const int lr  = tid >> 2;          // 0..63
    const int lc4 = (tid & 3) * 4;     // 0,4,8,12

    // compute mapping
    const int tx   = tid & 15;
    const int ty   = tid >> 4;
    const int row0 = ty * 8;
    const int col0 = tx * 8;

    const float* Xp0 = X  + (size_t)(bm + lr) * NIN + lc4;
    const float* Xp1 = X  + (size_t)(bm + lr + 64) * NIN + lc4;
    const int    n0  = bn + lr;
    const int    n1  = bn + lr + 64;
    const float* Wp0 = W1 + (size_t)n0 * NIN + lc4;
    const float* Wp1 = W1 + (size_t)n1 * NIN + lc4;
    const bool   v0  = (n0 < NHID);
    const bool   v1  = (n1 < NHID);

    float acc[8][8];
#pragma unroll
    for (int i = 0; i < 8; i++)
#pragma unroll
        for (int j = 0; j < 8; j++) acc[i][j] = 0.f;

    float4 pa0, pa1, pb0, pb1;   // prefetch registers

    // prologue: load tile 0 into buffer 0
    pa0 = *(const float4*)(Xp0);
    pa1 = *(const float4*)(Xp1);
    pb0 = v0 ? *(const float4*)(Wp0) : make_float4(0.f, 0.f, 0.f, 0.f);
    pb1 = v1 ? *(const float4*)(Wp1) : make_float4(0.f, 0.f, 0.f, 0.f);
    {
        float* as = As[0]; float* bs = Bs[0];
        as[(lc4 + 0) * LDA + lr]      = pa0.x;
        as[(lc4 + 1) * LDA + lr]      = pa0.y;
        as[(lc4 + 2) * LDA + lr]      = pa0.z;
        as[(lc4 + 3) * LDA + lr]      = pa0.w;
        as[(lc4 + 0) * LDA + lr + 64] = pa1.x;
        as[(lc4 + 1) * LDA + lr + 64] = pa1.y;
        as[(lc4 + 2) * LDA + lr + 64] = pa1.z;
        as[(lc4 + 3) * LDA + lr + 64] = pa1.w;
        bs[(lc4 + 0) * LDB + lr]      = pb0.x;
        bs[(lc4 + 1) * LDB + lr]      = pb0.y;
        bs[(lc4 + 2) * LDB + lr]      = pb0.z;
        bs[(lc4 + 3) * LDB + lr]      = pb0.w;
        bs[(lc4 + 0) * LDB + lr + 64] = pb1.x;
        bs[(lc4 + 1) * LDB + lr + 64] = pb1.y;
        bs[(lc4 + 2) * LDB + lr + 64] = pb1.z;
        bs[(lc4 + 3) * LDB + lr + 64] = pb1.w;
    }
    __syncthreads();

#pragma unroll 1
    for (int kt = 0; kt < NT; kt++) {
        const int cur = kt & 1;

        // prefetch next tile's gmem data (hidden behind 2048 fp instrs)
        if (kt + 1 < NT) {
            const int koff = (kt + 1) * BK;
            pa0 = *(const float4*)(Xp0 + koff);
            pa1 = *(const float4*)(Xp1 + koff);
            pb0 = v0 ? *(const float4*)(Wp0 + koff) : make_float4(0.f, 0.f, 0.f, 0.f);
            pb1 = v1 ? *(const float4*)(Wp1 + koff) : make_float4(0.f, 0.f, 0.f, 0.f);
        }

        // compute current tile: ascending k, unfused rn mul + rn add
        const float* as = As[cur];
        const float* bs = Bs[cur];
#pragma unroll
        for (int k = 0; k < BK; k++) {
            float a[8], b[8];
            *(float4*)(a)     = *(const float4*)&as[k * LDA + row0];
            *(float4*)(a + 4) = *(const float4*)&as[k * LDA + row0 + 4];
            *(float4*)(b)     = *(const float4*)&bs[k * LDB + col0];
            *(float4*)(b + 4) = *(const float4*)&bs[k * LDB + col0 + 4];
#pragma unroll
            for (int i = 0; i < 8; i++)
#pragma unroll
                for (int j = 0; j < 8; j++)
                    acc[i][j] = __fadd_rn(acc[i][j], __fmul_rn(a[i], b[j]));
        }

        // store prefetched tile into the other buffer
        if (kt + 1 < NT) {
            const int nxt = (kt + 1) & 1;
            float* asn = As[nxt]; float* bsn = Bs[nxt];
            asn[(lc4 + 0) * LDA + lr]      = pa0.x;
            asn[(lc4 + 1) * LDA + lr]      = pa0.y;
            asn[(lc4 + 2) * LDA + lr]      = pa0.z;
            asn[(lc4 + 3) * LDA + lr]      = pa0.w;
            asn[(lc4 + 0) * LDA + lr + 64] = pa1.x;
            asn[(lc4 + 1) * LDA + lr + 64] = pa1.y;
            asn[(lc4 + 2) * LDA + lr + 64] = pa1.z;
            asn[(lc4 + 3) * LDA + lr + 64] = pa1.w;
            bsn[(lc4 + 0) * LDB + lr]      = pb0.x;
            bsn[(lc4 + 1) * LDB + lr]      = pb0.y;
            bsn[(lc4 + 2) * LDB + lr]      = pb0.z;
            bsn[(lc4 + 3) * LDB + lr]      = pb0.w;
            bsn[(lc4 + 0) * LDB + lr + 64] = pb1.x;
            bsn[(lc4 + 1) * LDB + lr + 64] = pb1.y;
            bsn[(lc4 + 2) * LDB + lr + 64] = pb1.z;
            bsn[(lc4 + 3) * LDB + lr + 64] = pb1.w;
            __syncthreads();
        }
    }

    // epilogue: single rn bias add, store cur1
#pragma unroll
    for (int i = 0; i < 8; i++) {
        const int m = bm + row0 + i;
#pragma unroll
        for (int j = 0; j < 8; j++) {
            const int n = bn + col0 + j;
            if (n < NHID)
                g_cur1[(size_t)m * NHID + n] = __fadd_rn(acc[i][j], __ldg(&b1[n]));
        }
    }
}

// ---------------------------------------------------------------------------
// Kernel 2: layer-1 leaky-integrate recurrence; spk1 -> transposed bitmask.
// Strict rn ops, unfused, exact reference op order: ((B*mem)+cur)-reset.
// ---------------------------------------------------------------------------
__global__ void __launch_bounds__(256)
rec1_kernel()
{
    const int warp  = (blockIdx.x * blockDim.x + threadIdx.x) >> 5;
    const int lane  = threadIdx.x & 31;
    const int chunk = warp & 31;
    const int b     = warp >> 5;
    if (b >= BATCH) return;

    const int h = chunk * 32 + lane;
    const bool valid = (h < NHID);

    float mem = 0.f;
#pragma unroll
    for (int t = 0; t < NUM_STEPS; t++) {
        const float c = valid ? g_cur1[((size_t)t * BATCH + b) * NHID + h] : -1.f;
        const float rst = (mem > THRESH) ? THRESH : 0.f;
        mem = __fsub_rn(__fadd_rn(__fmul_rn(BETA, mem), c), rst);
        const uint32_t w = __ballot_sync(0xffffffffu, mem > THRESH);
        if (lane == 0)
            g_maskT[(size_t)chunk * MTOT + (size_t)t * BATCH + b] = w;
    }
}

// ---------------------------------------------------------------------------
// Kernel 3: cur2 = spk1 @ W2^T + b2.  One thread per row, ascending-h chain.
// With spk in {0,1}, rn(spk*w) is exact, so the FMA chain is bit-identical
// to an unfused ascending chain.
// ---------------------------------------------------------------------------
#define W2LD 12

__global__ void __launch_bounds__(256)
gemm2_kernel(const float* __restrict__ W2, const float* __restrict__ b2)
{
    __shared__ float W2t[1000 * W2LD];   // [h][o], padded
    for (int i = threadIdx.x; i < NOUT * NHID; i += 256) {
        const int o = i / NHID, h = i - o * NHID;
        W2t[h * W2LD + o] = W2[i];
    }
    __syncthreads();

    const int row = blockIdx.x * 256 + threadIdx.x;   // 0..102399

    float acc[NOUT];
#pragma unroll
    for (int o = 0; o < NOUT; o++) acc[o] = 0.f;

#pragma unroll 1
    for (int wd = 0; wd < 32; wd++) {
        const uint32_t w = g_maskT[(size_t)wd * MTOT + row];
        const int nb = (wd < 31) ? 32 : (NHID - 31 * 32);   // 32 or 8
#pragma unroll 8
        for (int bit = 0; bit < nb; bit++) {
            const float f = (float)((w >> bit) & 1u);
            const int h = wd * 32 + bit;
            const float* wrow = &W2t[h * W2LD];
            float4 w0 = *(const float4*)(wrow);
            float4 w1 = *(const float4*)(wrow + 4);
            float2 w2v = *(const float2*)(wrow + 8);
            acc[0] = __fmaf_rn(f, w0.x, acc[0]);
            acc[1] = __fmaf_rn(f, w0.y, acc[1]);
            acc[2] = __fmaf_rn(f, w0.z, acc[2]);
            acc[3] = __fmaf_rn(f, w0.w, acc[3]);
            acc[4] = __fmaf_rn(f, w1.x, acc[4]);
            acc[5] = __fmaf_rn(f, w1.y, acc[5]);
            acc[6] = __fmaf_rn(f, w1.z, acc[6]);
            acc[7] = __fmaf_rn(f, w1.w, acc[7]);
            acc[8] = __fmaf_rn(f, w2v.x, acc[8]);
            acc[9] = __fmaf_rn(f, w2v.y, acc[9]);
        }
    }

    float* out = g_cur2 + (size_t)row * NOUT;
#pragma unroll
    for (int o = 0; o < NOUT; o++)
        out[o] = __fadd_rn(acc[o], __ldg(&b2[o]));
}

// ---------------------------------------------------------------------------
// Kernel 4: layer-2 recurrence + write spk_rec / mem_rec outputs.
// Output layout: [spk_rec (25,4096,10) | mem_rec (25,4096,10)]
// ---------------------------------------------------------------------------
__global__ void __launch_bounds__(256)
rec2_kernel(float* __restrict__ out)
{
    const int idx = blockIdx.x * blockDim.x + threadIdx.x;   // b*10 + o
    if (idx >= BATCH * NOUT) return;

    float mem = 0.f;
#pragma unroll
    for (int t = 0; t < NUM_STEPS; t++) {
        const float c   = g_cur2[(size_t)t * (BATCH * NOUT) + idx];
        const float rst = (mem > THRESH) ? THRESH : 0.f;
        mem = __fsub_rn(__fadd_rn(__fmul_rn(BETA, mem), c), rst);
        const float spk = (mem > THRESH) ? 1.f : 0.f;
        out[(size_t)t * (BATCH * NOUT) + idx] = spk;
        out[(size_t)NUM_STEPS * BATCH * NOUT + (size_t)t * (BATCH * NOUT) + idx] = mem;
    }
}

// ---------------------------------------------------------------------------
extern "C" void kernel_launch(void* const* d_in, const int* in_sizes, int n_in,
                              void* d_out, int out_size)
{
    const float* x  = (const float*)d_in[0];   // [25,4096,784]
    const float* W1 = (const float*)d_in[1];   // [1000,784]
    const float* b1 = (const float*)d_in[2];   // [1000]
    const float* W2 = (const float*)d_in[3];   // [10,1000]
    const float* b2 = (const float*)d_in[4];   // [10]
    float* out = (float*)d_out;

    dim3 g1((NHID + BN - 1) / BN, MTOT / BM);  // (8, 800)
    gemm1_kernel<<<g1, 256>>>(x, W1, b1);

    rec1_kernel<<<(BATCH * 32) / 8, 256>>>();

    gemm2_kernel<<<MTOT / 256, 256>>>(W2, b2);

    rec2_kernel<<<(BATCH * NOUT + 255) / 256, 256>>>(out);
}